// round 12
// baseline (speedup 1.0000x reference)
#include <cuda_runtime.h>

#define C 32
#define H 128
#define W 256
#define YS 36        // y_sh row stride (144B): lane bank stride 4 -> conflict-free LDS.128
#define YROWS 257    // rows 0..255 = y columns; row 256 = zero row (both boundaries)
#define GO 66
#define GS 67        // gather lane stride 67 == bank stride 3 -> conflict-free
#define GROWS 257    // rows 0..255 real; row 256 pads the w=255 b-store
#define NT 256
#define PF 8         // disp prefetch depth

typedef unsigned long long u64;

__device__ __forceinline__ u64 pack2(float lo, float hi) {
    u64 r; asm("mov.b64 %0, {%1, %2};" : "=l"(r) : "f"(lo), "f"(hi)); return r;
}
__device__ __forceinline__ void ffma2(u64& acc, u64 a, u64 b) {
    asm("fma.rn.f32x2 %0, %1, %2, %0;" : "+l"(acc) : "l"(a), "l"(b));
}
__device__ __forceinline__ u64 add2(u64 a, u64 b) {
    u64 r; asm("add.rn.f32x2 %0, %1, %2;" : "=l"(r) : "l"(a), "l"(b)); return r;
}
__device__ __forceinline__ float hadd2(u64 v) {
    float lo, hi; asm("mov.b64 {%0, %1}, %2;" : "=f"(lo), "=f"(hi) : "l"(v)); return lo + hi;
}

__global__ __launch_bounds__(NT, 2)
void cost_volume_kernel(const float* __restrict__ x, const float* __restrict__ y,
                        const float* __restrict__ disp, float* __restrict__ out,
                        int D) {
    extern __shared__ float sm[];
    float* y_sh = sm;                  // YROWS * YS ([col][c]; row 256 = zeros)
    float* G_sh = sm + YROWS * YS;     // GROWS * GS banded Gram

    const int bh = blockIdx.x;
    const int b = bh / H;
    const int h = bh - b * H;
    const int tid = threadIdx.x;
    const size_t HW = (size_t)H * W;
    const float* ybase = y + ((size_t)b * C * H + h) * W;
    const float* xbase = x + ((size_t)b * C * H + h) * W;

    // ---- Phase 1: stage y row transposed (row r = y column r). Row 256 is
    // the zero row implementing the reference's zero-padding mask.
    {
        const float* src = ybase + tid;
        float* dst = y_sh + tid * YS;
        #pragma unroll
        for (int c = 0; c < C; c += 4) {
            float v0 = src[(size_t)(c + 0) * HW];
            float v1 = src[(size_t)(c + 1) * HW];
            float v2 = src[(size_t)(c + 2) * HW];
            float v3 = src[(size_t)(c + 3) * HW];
            *(float4*)(dst + c) = make_float4(v0, v1, v2, v3);
        }
    }
    if (tid < YS) y_sh[256 * YS + tid] = 0.0f;

    // x columns w and w+1, all 32 channels, packed for FFMA2.
    const int w = tid;                // blockDim.x == W
    const bool has_b = (w + 1 < W);
    u64 xa[16], xb[16];
    #pragma unroll
    for (int k = 0; k < 16; k++) {
        float a0 = xbase[(size_t)(2 * k) * HW + w];
        float a1 = xbase[(size_t)(2 * k + 1) * HW + w];
        xa[k] = pack2(a0, a1);
        float b0 = has_b ? xbase[(size_t)(2 * k) * HW + w + 1] : 0.f;
        float b1 = has_b ? xbase[(size_t)(2 * k + 1) * HW + w + 1] : 0.f;
        xb[k] = pack2(b0, b1);
    }
    __syncthreads();

    // ---- Phase 2: banded Gram  G[w][o] = sum_c x[c][w] * y[c][w+o-64]
    // Anti-diagonal pairing: (w, o0) and (w+1, o0-1) share y column w+o0-64.
    // r < 0 clamps to the zero row; r == 256 (w=255,o0=65) is already zero.
    float* ga = G_sh + w * GS;
    float* gb = G_sh + (w + 1) * GS;
    #pragma unroll 2
    for (int o0 = 1; o0 <= 65; o0 += 2) {
        int r = w + o0 - 64;
        if (r < 0) r = 256;
        const ulonglong2* yp = (const ulonglong2*)(y_sh + r * YS);
        ulonglong2 q0 = yp[0], q1 = yp[1], q2 = yp[2], q3 = yp[3];
        ulonglong2 q4 = yp[4], q5 = yp[5], q6 = yp[6], q7 = yp[7];
        u64 a0 = 0, a1 = 0, a2 = 0, a3 = 0;
        u64 b0 = 0, b1 = 0, b2 = 0, b3 = 0;
        ffma2(a0, xa[0],  q0.x);  ffma2(b0, xb[0],  q0.x);
        ffma2(a1, xa[1],  q0.y);  ffma2(b1, xb[1],  q0.y);
        ffma2(a2, xa[2],  q1.x);  ffma2(b2, xb[2],  q1.x);
        ffma2(a3, xa[3],  q1.y);  ffma2(b3, xb[3],  q1.y);
        ffma2(a0, xa[4],  q2.x);  ffma2(b0, xb[4],  q2.x);
        ffma2(a1, xa[5],  q2.y);  ffma2(b1, xb[5],  q2.y);
        ffma2(a2, xa[6],  q3.x);  ffma2(b2, xb[6],  q3.x);
        ffma2(a3, xa[7],  q3.y);  ffma2(b3, xb[7],  q3.y);
        ffma2(a0, xa[8],  q4.x);  ffma2(b0, xb[8],  q4.x);
        ffma2(a1, xa[9],  q4.y);  ffma2(b1, xb[9],  q4.y);
        ffma2(a2, xa[10], q5.x);  ffma2(b2, xb[10], q5.x);
        ffma2(a3, xa[11], q5.y);  ffma2(b3, xb[11], q5.y);
        ffma2(a0, xa[12], q6.x);  ffma2(b0, xb[12], q6.x);
        ffma2(a1, xa[13], q6.y);  ffma2(b1, xb[13], q6.y);
        ffma2(a2, xa[14], q7.x);  ffma2(b2, xb[14], q7.x);
        ffma2(a3, xa[15], q7.y);  ffma2(b3, xb[15], q7.y);
        ga[o0]     = hadd2(add2(add2(a0, a1), add2(a2, a3)));
        gb[o0 - 1] = hadd2(add2(add2(b0, b1), add2(b2, b3)));
    }
    // Cleanup: entries (w=0, even o): zero except the single real dot at o=64.
    if (tid < 33) {
        int o = 2 * tid;
        float s = 0.f;
        if (o == 64) {
            #pragma unroll
            for (int c = 0; c < C; c++)
                s = fmaf(xbase[(size_t)c * HW], y_sh[0 * YS + c], s);
        }
        G_sh[o] = s;
    }

    // ---- Phase 3: column-owner gather. Thread w handles all D disparities of
    // its own column: gather LDS lanes have consecutive w -> bank stride 3 ->
    // conflict-free; disp/out accesses are W-contiguous per d -> coalesced.
    const float* dcol = disp + ((size_t)b * D * H + h) * W + w;
    float* ocol = out + ((size_t)b * D * H + h) * W + w;
    const float wf = (float)w;

    // Rolling prefetch: first PF disp values issued BEFORE the barrier so
    // their latency hides under other warps' phase-2 tail.
    float dpf[PF];
    #pragma unroll
    for (int k = 0; k < PF; k++)
        dpf[k] = dcol[(size_t)k * HW];
    __syncthreads();

    // disp in [0,64) => o = floor(w-disp)-w+64 in [0,64], o+1 in [1,65]:
    // always in-band -> no guards.
    #pragma unroll 4
    for (int d = 0; d < D; d++) {
        float dvj = dpf[0];
        #pragma unroll
        for (int k = 0; k < PF - 1; k++) dpf[k] = dpf[k + 1];
        int dn = d + PF;
        if (dn < D) dpf[PF - 1] = dcol[(size_t)dn * HW];
        float px = wf - dvj;
        float x0f = floorf(px);
        float fx = px - x0f;
        int o = (int)x0f - w + 64;
        float g0 = ga[o];
        float g1 = ga[o + 1];
        ocol[(size_t)d * HW] = (g0 + (g1 - g0) * fx) * (1.0f / C);
    }
}

extern "C" void kernel_launch(void* const* d_in, const int* in_sizes, int n_in,
                              void* d_out, int out_size) {
    const float* x = (const float*)d_in[0];
    const float* y = (const float*)d_in[1];
    const float* disp = (const float*)d_in[2];
    int B = in_sizes[0] / (C * H * W);
    int D = in_sizes[2] / (B * H * W);
    int smem = (YROWS * YS + GROWS * GS) * (int)sizeof(float);
    cudaFuncSetAttribute(cost_volume_kernel,
                         cudaFuncAttributeMaxDynamicSharedMemorySize, smem);
    cost_volume_kernel<<<B * H, NT, smem>>>(x, y, disp, (float*)d_out, D);
}

// round 13
// speedup vs baseline: 1.1426x; 1.1426x over previous
#include <cuda_runtime.h>

#define C 32
#define H 128
#define W 256
#define YS 36        // y_sh row stride (144B): lane bank stride 4 -> conflict-free LDS.128
#define YROWS 257    // rows 0..255 = y columns; row 256 = zero row (both boundaries)
#define GO 66
#define GS 67
#define GROWS 257    // rows 0..255 real; row 256 pads the w=255 b-store
#define NT 256

typedef unsigned long long u64;

__device__ __forceinline__ u64 pack2(float lo, float hi) {
    u64 r; asm("mov.b64 %0, {%1, %2};" : "=l"(r) : "f"(lo), "f"(hi)); return r;
}
__device__ __forceinline__ void ffma2(u64& acc, u64 a, u64 b) {
    asm("fma.rn.f32x2 %0, %1, %2, %0;" : "+l"(acc) : "l"(a), "l"(b));
}
__device__ __forceinline__ u64 add2(u64 a, u64 b) {
    u64 r; asm("add.rn.f32x2 %0, %1, %2;" : "=l"(r) : "l"(a), "l"(b)); return r;
}
__device__ __forceinline__ float hadd2(u64 v) {
    float lo, hi; asm("mov.b64 {%0, %1}, %2;" : "=f"(lo), "=f"(hi) : "l"(v)); return lo + hi;
}

__global__ __launch_bounds__(NT, 2)
void cost_volume_kernel(const float* __restrict__ x, const float* __restrict__ y,
                        const float* __restrict__ disp, float* __restrict__ out,
                        int D) {
    extern __shared__ float sm[];
    float* y_sh = sm;                  // YROWS * YS ([col][c]; row 256 = zeros)
    float* G_sh = sm + YROWS * YS;     // GROWS * GS banded Gram

    const int bh = blockIdx.x;
    const int b = bh / H;
    const int h = bh - b * H;
    const int tid = threadIdx.x;
    const size_t HW = (size_t)H * W;
    const float* ybase = y + ((size_t)b * C * H + h) * W;
    const float* xbase = x + ((size_t)b * C * H + h) * W;

    // ---- Phase 1: stage y row transposed (row r = y column r). Row 256 is
    // the zero row implementing the reference's zero-padding mask.
    {
        const float* src = ybase + tid;
        float* dst = y_sh + tid * YS;
        #pragma unroll
        for (int c = 0; c < C; c += 4) {
            float v0 = src[(size_t)(c + 0) * HW];
            float v1 = src[(size_t)(c + 1) * HW];
            float v2 = src[(size_t)(c + 2) * HW];
            float v3 = src[(size_t)(c + 3) * HW];
            *(float4*)(dst + c) = make_float4(v0, v1, v2, v3);
        }
    }
    if (tid < YS) y_sh[256 * YS + tid] = 0.0f;

    // x columns w and w+1, all 32 channels, packed for FFMA2.
    const int w = tid;                // blockDim.x == W
    const bool has_b = (w + 1 < W);
    u64 xa[16], xb[16];
    #pragma unroll
    for (int k = 0; k < 16; k++) {
        float a0 = xbase[(size_t)(2 * k) * HW + w];
        float a1 = xbase[(size_t)(2 * k + 1) * HW + w];
        xa[k] = pack2(a0, a1);
        float b0 = has_b ? xbase[(size_t)(2 * k) * HW + w + 1] : 0.f;
        float b1 = has_b ? xbase[(size_t)(2 * k + 1) * HW + w + 1] : 0.f;
        xb[k] = pack2(b0, b1);
    }
    __syncthreads();

    // ---- Phase 2: banded Gram  G[w][o] = sum_c x[c][w] * y[c][w+o-64]
    // Anti-diagonal pairing: (w, o0) and (w+1, o0-1) share y column w+o0-64.
    // Software-pipelined halves: [ld half1 | fma half0 | ld next half0 |
    // fma half1 | store]. Each LDS batch gets ~16 FFMA2 of cover before its
    // first consumer; liveness stays at 2 half-buffers (32 regs).
    float* ga = G_sh + w * GS;
    float* gb = G_sh + (w + 1) * GS;
    ulonglong2 c0, c1, c2, c3;
    {
        int r = w + 1 - 64;
        if ((unsigned)r > 255u) r = 256;
        const ulonglong2* yp = (const ulonglong2*)(y_sh + r * YS);
        c0 = yp[0]; c1 = yp[1]; c2 = yp[2]; c3 = yp[3];
    }
    #pragma unroll 2
    for (int o0 = 1; o0 <= 65; o0 += 2) {
        int r = w + o0 - 64;
        if ((unsigned)r > 255u) r = 256;
        const ulonglong2* yp = (const ulonglong2*)(y_sh + r * YS);
        ulonglong2 n0 = yp[4], n1 = yp[5], n2 = yp[6], n3 = yp[7];  // half1
        u64 a0 = 0, a1 = 0, a2 = 0, a3 = 0;
        u64 b0 = 0, b1 = 0, b2 = 0, b3 = 0;
        // half0: channels 0..15
        ffma2(a0, xa[0], c0.x);  ffma2(b0, xb[0], c0.x);
        ffma2(a1, xa[1], c0.y);  ffma2(b1, xb[1], c0.y);
        ffma2(a2, xa[2], c1.x);  ffma2(b2, xb[2], c1.x);
        ffma2(a3, xa[3], c1.y);  ffma2(b3, xb[3], c1.y);
        ffma2(a0, xa[4], c2.x);  ffma2(b0, xb[4], c2.x);
        ffma2(a1, xa[5], c2.y);  ffma2(b1, xb[5], c2.y);
        ffma2(a2, xa[6], c3.x);  ffma2(b2, xb[6], c3.x);
        ffma2(a3, xa[7], c3.y);  ffma2(b3, xb[7], c3.y);
        // prefetch half0 of the NEXT iteration (c regs are dead now)
        {
            int rn = w + o0 + 2 - 64;
            if ((unsigned)rn > 255u) rn = 256;     // also covers the o0=65 tail
            const ulonglong2* ypn = (const ulonglong2*)(y_sh + rn * YS);
            c0 = ypn[0]; c1 = ypn[1]; c2 = ypn[2]; c3 = ypn[3];
        }
        // half1: channels 16..31
        ffma2(a0, xa[8],  n0.x);  ffma2(b0, xb[8],  n0.x);
        ffma2(a1, xa[9],  n0.y);  ffma2(b1, xb[9],  n0.y);
        ffma2(a2, xa[10], n1.x);  ffma2(b2, xb[10], n1.x);
        ffma2(a3, xa[11], n1.y);  ffma2(b3, xb[11], n1.y);
        ffma2(a0, xa[12], n2.x);  ffma2(b0, xb[12], n2.x);
        ffma2(a1, xa[13], n2.y);  ffma2(b1, xb[13], n2.y);
        ffma2(a2, xa[14], n3.x);  ffma2(b2, xb[14], n3.x);
        ffma2(a3, xa[15], n3.y);  ffma2(b3, xb[15], n3.y);
        ga[o0]     = hadd2(add2(add2(a0, a1), add2(a2, a3)));
        gb[o0 - 1] = hadd2(add2(add2(b0, b1), add2(b2, b3)));
    }
    // Cleanup: entries (w=0, even o): zero except the single real dot at o=64.
    if (tid < 33) {
        int o = 2 * tid;
        float s = 0.f;
        if (o == 64) {
            #pragma unroll
            for (int c = 0; c < C; c++)
                s = fmaf(xbase[(size_t)c * HW], y_sh[0 * YS + c], s);
        }
        G_sh[o] = s;
    }

    // ---- Phase 3 prologue: disp loads before the barrier (latency hidden
    // under other warps' phase-2 tail).
    const float* dbase = disp + ((size_t)b * D * H + h) * W;
    float* obase = out + ((size_t)b * D * H + h) * W;

    // disp in [0,64) => o = floor(w-disp)-w+64 in [0,64], o+1 in [1,65]:
    // always in-band -> no guards.
    if (D == 48) {
        float4 dv[12];
        #pragma unroll
        for (int k = 0; k < 12; k++) {
            int i = tid + k * NT;
            int d = i >> 6;               // 64 float4 per d
            int w4 = (i & 63) << 2;
            dv[k] = *(const float4*)(dbase + (size_t)d * HW + w4);
        }
        __syncthreads();
        #pragma unroll
        for (int k = 0; k < 12; k++) {
            int i = tid + k * NT;
            int d = i >> 6;
            int w4 = (i & 63) << 2;
            float4 res;
            #pragma unroll
            for (int j = 0; j < 4; j++) {
                int ww = w4 + j;
                float px = (float)ww - (&dv[k].x)[j];
                float x0f = floorf(px);
                float fx = px - x0f;
                int o = (int)x0f - ww + 64;
                float g0 = G_sh[ww * GS + o];
                float g1 = G_sh[ww * GS + o + 1];
                (&res.x)[j] = (g0 + (g1 - g0) * fx) * (1.0f / C);
            }
            *(float4*)(obase + (size_t)d * HW + w4) = res;
        }
    } else {
        __syncthreads();
        const int total4 = D * (W / 4);
        #pragma unroll 4
        for (int i = tid; i < total4; i += NT) {
            int d = i >> 6;
            int w4 = (i & 63) << 2;
            float4 dvv = *(const float4*)(dbase + (size_t)d * HW + w4);
            float4 res;
            #pragma unroll
            for (int j = 0; j < 4; j++) {
                int ww = w4 + j;
                float px = (float)ww - (&dvv.x)[j];
                float x0f = floorf(px);
                float fx = px - x0f;
                int o = (int)x0f - ww + 64;
                float g0 = ((unsigned)o < GO) ? G_sh[ww * GS + o] : 0.f;
                float g1 = ((unsigned)(o + 1) < GO) ? G_sh[ww * GS + o + 1] : 0.f;
                (&res.x)[j] = (g0 + (g1 - g0) * fx) * (1.0f / C);
            }
            *(float4*)(obase + (size_t)d * HW + w4) = res;
        }
    }
}

extern "C" void kernel_launch(void* const* d_in, const int* in_sizes, int n_in,
                              void* d_out, int out_size) {
    const float* x = (const float*)d_in[0];
    const float* y = (const float*)d_in[1];
    const float* disp = (const float*)d_in[2];
    int B = in_sizes[0] / (C * H * W);
    int D = in_sizes[2] / (B * H * W);
    int smem = (YROWS * YS + GROWS * GS) * (int)sizeof(float);
    cudaFuncSetAttribute(cost_volume_kernel,
                         cudaFuncAttributeMaxDynamicSharedMemorySize, smem);
    cost_volume_kernel<<<B * H, NT, smem>>>(x, y, disp, (float*)d_out, D);
}

// round 14
// speedup vs baseline: 1.1496x; 1.0061x over previous
#include <cuda_runtime.h>

#define C 32
#define H 128
#define W 256
#define YS 36        // y_sh row stride (144B): lane bank stride 4 -> conflict-free LDS.128
#define YROWS 257    // rows 0..255 = y columns; row 256 = zero row (both boundaries)
#define GO 66
#define GS 67        // gather: lane w-stride 1 -> bank stride 3 -> conflict-free
#define GROWS 257    // rows 0..255 real; row 256 pads the w=255 b-store
#define NT 256

typedef unsigned long long u64;

__device__ __forceinline__ u64 pack2(float lo, float hi) {
    u64 r; asm("mov.b64 %0, {%1, %2};" : "=l"(r) : "f"(lo), "f"(hi)); return r;
}
__device__ __forceinline__ void ffma2(u64& acc, u64 a, u64 b) {
    asm("fma.rn.f32x2 %0, %1, %2, %0;" : "+l"(acc) : "l"(a), "l"(b));
}
__device__ __forceinline__ u64 add2(u64 a, u64 b) {
    u64 r; asm("add.rn.f32x2 %0, %1, %2;" : "=l"(r) : "l"(a), "l"(b)); return r;
}
__device__ __forceinline__ float hadd2(u64 v) {
    float lo, hi; asm("mov.b64 {%0, %1}, %2;" : "=f"(lo), "=f"(hi) : "l"(v)); return lo + hi;
}

__global__ __launch_bounds__(NT, 2)
void cost_volume_kernel(const float* __restrict__ x, const float* __restrict__ y,
                        const float* __restrict__ disp, float* __restrict__ out,
                        int D) {
    extern __shared__ float sm[];
    float* y_sh = sm;                  // YROWS * YS ([col][c]; row 256 = zeros)
    float* G_sh = sm + YROWS * YS;     // GROWS * GS banded Gram

    const int bh = blockIdx.x;
    const int b = bh / H;
    const int h = bh - b * H;
    const int tid = threadIdx.x;
    const size_t HW = (size_t)H * W;
    const float* ybase = y + ((size_t)b * C * H + h) * W;
    const float* xbase = x + ((size_t)b * C * H + h) * W;

    // ---- Phase 1: stage y row transposed (row r = y column r). Row 256 is
    // the zero row implementing the reference's zero-padding mask.
    {
        const float* src = ybase + tid;
        float* dst = y_sh + tid * YS;
        #pragma unroll
        for (int c = 0; c < C; c += 4) {
            float v0 = src[(size_t)(c + 0) * HW];
            float v1 = src[(size_t)(c + 1) * HW];
            float v2 = src[(size_t)(c + 2) * HW];
            float v3 = src[(size_t)(c + 3) * HW];
            *(float4*)(dst + c) = make_float4(v0, v1, v2, v3);
        }
    }
    if (tid < YS) y_sh[256 * YS + tid] = 0.0f;

    // x columns w and w+1, all 32 channels, packed for FFMA2.
    const int w = tid;                // blockDim.x == W
    const bool has_b = (w + 1 < W);
    u64 xa[16], xb[16];
    #pragma unroll
    for (int k = 0; k < 16; k++) {
        float a0 = xbase[(size_t)(2 * k) * HW + w];
        float a1 = xbase[(size_t)(2 * k + 1) * HW + w];
        xa[k] = pack2(a0, a1);
        float b0 = has_b ? xbase[(size_t)(2 * k) * HW + w + 1] : 0.f;
        float b1 = has_b ? xbase[(size_t)(2 * k + 1) * HW + w + 1] : 0.f;
        xb[k] = pack2(b0, b1);
    }
    __syncthreads();

    // ---- Phase 2: banded Gram  G[w][o] = sum_c x[c][w] * y[c][w+o-64]
    // Anti-diagonal pairing: (w, o0) and (w+1, o0-1) share y column w+o0-64.
    // Software-pipelined halves (see R13).
    float* ga = G_sh + w * GS;
    float* gb = G_sh + (w + 1) * GS;
    ulonglong2 c0, c1, c2, c3;
    {
        int r = w + 1 - 64;
        if ((unsigned)r > 255u) r = 256;
        const ulonglong2* yp = (const ulonglong2*)(y_sh + r * YS);
        c0 = yp[0]; c1 = yp[1]; c2 = yp[2]; c3 = yp[3];
    }
    #pragma unroll 2
    for (int o0 = 1; o0 <= 65; o0 += 2) {
        int r = w + o0 - 64;
        if ((unsigned)r > 255u) r = 256;
        const ulonglong2* yp = (const ulonglong2*)(y_sh + r * YS);
        ulonglong2 n0 = yp[4], n1 = yp[5], n2 = yp[6], n3 = yp[7];  // half1
        u64 a0 = 0, a1 = 0, a2 = 0, a3 = 0;
        u64 b0 = 0, b1 = 0, b2 = 0, b3 = 0;
        // half0: channels 0..15
        ffma2(a0, xa[0], c0.x);  ffma2(b0, xb[0], c0.x);
        ffma2(a1, xa[1], c0.y);  ffma2(b1, xb[1], c0.y);
        ffma2(a2, xa[2], c1.x);  ffma2(b2, xb[2], c1.x);
        ffma2(a3, xa[3], c1.y);  ffma2(b3, xb[3], c1.y);
        ffma2(a0, xa[4], c2.x);  ffma2(b0, xb[4], c2.x);
        ffma2(a1, xa[5], c2.y);  ffma2(b1, xb[5], c2.y);
        ffma2(a2, xa[6], c3.x);  ffma2(b2, xb[6], c3.x);
        ffma2(a3, xa[7], c3.y);  ffma2(b3, xb[7], c3.y);
        // prefetch half0 of the NEXT iteration (c regs are dead now)
        {
            int rn = w + o0 + 2 - 64;
            if ((unsigned)rn > 255u) rn = 256;     // also covers the o0=65 tail
            const ulonglong2* ypn = (const ulonglong2*)(y_sh + rn * YS);
            c0 = ypn[0]; c1 = ypn[1]; c2 = ypn[2]; c3 = ypn[3];
        }
        // half1: channels 16..31
        ffma2(a0, xa[8],  n0.x);  ffma2(b0, xb[8],  n0.x);
        ffma2(a1, xa[9],  n0.y);  ffma2(b1, xb[9],  n0.y);
        ffma2(a2, xa[10], n1.x);  ffma2(b2, xb[10], n1.x);
        ffma2(a3, xa[11], n1.y);  ffma2(b3, xb[11], n1.y);
        ffma2(a0, xa[12], n2.x);  ffma2(b0, xb[12], n2.x);
        ffma2(a1, xa[13], n2.y);  ffma2(b1, xb[13], n2.y);
        ffma2(a2, xa[14], n3.x);  ffma2(b2, xb[14], n3.x);
        ffma2(a3, xa[15], n3.y);  ffma2(b3, xb[15], n3.y);
        ga[o0]     = hadd2(add2(add2(a0, a1), add2(a2, a3)));
        gb[o0 - 1] = hadd2(add2(add2(b0, b1), add2(b2, b3)));
    }
    // Cleanup: entries (w=0, even o): zero except the single real dot at o=64.
    if (tid < 33) {
        int o = 2 * tid;
        float s = 0.f;
        if (o == 64) {
            #pragma unroll
            for (int c = 0; c < C; c++)
                s = fmaf(xbase[(size_t)c * HW], y_sh[0 * YS + c], s);
        }
        G_sh[o] = s;
    }

    // ---- Phase 3: strided-w ownership. Thread (q, g) owns w in {q, q+64,
    // q+128, q+192} and d in [12g, 12g+12). Lanes have consecutive w ->
    // gather LDS bank-stride 3 (conflict-free) AND coalesced scalar LDG/STG.
    const float* dbase = disp + ((size_t)b * D * H + h) * W;
    float* obase = out + ((size_t)b * D * H + h) * W;

    // disp in [0,64) => o in [0,64], o+1 in [1,65]: always in-band, no guards.
    if (D == 48) {
        const int q = tid & 63;
        const int d0 = (tid >> 6) * 12;
        float dv[12];
        #pragma unroll
        for (int j = 0; j < 12; j++)               // slot 0 prefetch (w = q),
            dv[j] = dbase[(size_t)(d0 + j) * HW + q];  // issued BEFORE the barrier
        __syncthreads();
        #pragma unroll
        for (int s = 0; s < 4; s++) {
            const int w3 = q + s * 64;
            float dnx[12];
            if (s < 3) {
                #pragma unroll
                for (int j = 0; j < 12; j++)       // rolling prefetch, next slot
                    dnx[j] = dbase[(size_t)(d0 + j) * HW + w3 + 64];
            }
            const float* gr = G_sh + w3 * GS;
            const float wf = (float)w3;
            #pragma unroll
            for (int j = 0; j < 12; j++) {
                float px = wf - dv[j];
                float x0f = floorf(px);
                float fx = px - x0f;
                int o = (int)x0f - w3 + 64;
                float g0 = gr[o];
                float g1 = gr[o + 1];
                obase[(size_t)(d0 + j) * HW + w3] = (g0 + (g1 - g0) * fx) * (1.0f / C);
            }
            if (s < 3) {
                #pragma unroll
                for (int j = 0; j < 12; j++) dv[j] = dnx[j];
            }
        }
    } else {
        __syncthreads();
        const int total4 = D * (W / 4);
        #pragma unroll 4
        for (int i = tid; i < total4; i += NT) {
            int d = i >> 6;
            int w4 = (i & 63) << 2;
            float4 dvv = *(const float4*)(dbase + (size_t)d * HW + w4);
            float4 res;
            #pragma unroll
            for (int j = 0; j < 4; j++) {
                int ww = w4 + j;
                float px = (float)ww - (&dvv.x)[j];
                float x0f = floorf(px);
                float fx = px - x0f;
                int o = (int)x0f - ww + 64;
                float g0 = ((unsigned)o < GO) ? G_sh[ww * GS + o] : 0.f;
                float g1 = ((unsigned)(o + 1) < GO) ? G_sh[ww * GS + o + 1] : 0.f;
                (&res.x)[j] = (g0 + (g1 - g0) * fx) * (1.0f / C);
            }
            *(float4*)(obase + (size_t)d * HW + w4) = res;
        }
    }
}

extern "C" void kernel_launch(void* const* d_in, const int* in_sizes, int n_in,
                              void* d_out, int out_size) {
    const float* x = (const float*)d_in[0];
    const float* y = (const float*)d_in[1];
    const float* disp = (const float*)d_in[2];
    int B = in_sizes[0] / (C * H * W);
    int D = in_sizes[2] / (B * H * W);
    int smem = (YROWS * YS + GROWS * GS) * (int)sizeof(float);
    cudaFuncSetAttribute(cost_volume_kernel,
                         cudaFuncAttributeMaxDynamicSharedMemorySize, smem);
    cost_volume_kernel<<<B * H, NT, smem>>>(x, y, disp, (float*)d_out, D);
}